// round 1
// baseline (speedup 1.0000x reference)
#include <cuda_runtime.h>
#include <math.h>

// ---------------- problem constants ----------------
#define N_NODES 6000
#define E_EDGES 192000
#define CIN     32
#define CHID    64
#define KK      125          // 5^3 spline kernels
#define NX      192          // 3 gates * 64 (xr | xz | xn)
#define NH      128          // 2 gates * 64 (hr | hz)
#define KX      (KK * CIN)   // 4000
#define KH      (KK * CHID)  // 8000

// ---------------- static device scratch (no allocs allowed) ----------------
__device__ float g_Tx[N_NODES * KK * CIN];      //  96 MB
__device__ float g_Th[N_NODES * KK * CHID];     // 192 MB
__device__ float g_deg[N_NODES];
__device__ float g_convx[N_NODES * NX];
__device__ float g_convh[N_NODES * NH];
__device__ float g_Wx[KX * NX];                 // 3 MB  (concat xr|xz|xn)
__device__ float g_Wh[KH * NH];                 // 4 MB  (concat hr|hz)

// ---------------- helpers ----------------
__device__ __forceinline__ void red_add_f4(float* p, float a, float b, float c, float d) {
    asm volatile("red.global.add.v4.f32 [%0], {%1,%2,%3,%4};"
                 :: "l"(p), "f"(a), "f"(b), "f"(c), "f"(d) : "memory");
}

// ---------------- zero T buffers + deg ----------------
__global__ void zero_kernel() {
    long long i = (long long)blockIdx.x * blockDim.x + threadIdx.x;
    long long stride = (long long)gridDim.x * blockDim.x;
    float4 z = make_float4(0.f, 0.f, 0.f, 0.f);
    float4* tx = reinterpret_cast<float4*>(g_Tx);
    float4* th = reinterpret_cast<float4*>(g_Th);
    const long long nx4 = (long long)N_NODES * KK * CIN / 4;
    const long long nh4 = (long long)N_NODES * KK * CHID / 4;
    for (long long j = i; j < nx4; j += stride) tx[j] = z;
    for (long long j = i; j < nh4; j += stride) th[j] = z;
    if (i < N_NODES) g_deg[i] = 0.f;
}

// ---------------- pack concatenated weight matrices ----------------
__global__ void pack_kernel(const float* __restrict__ Wxr, const float* __restrict__ Wxz,
                            const float* __restrict__ Wxn, const float* __restrict__ Whr,
                            const float* __restrict__ Whz) {
    int stride = gridDim.x * blockDim.x;
    for (int i = blockIdx.x * blockDim.x + threadIdx.x; i < KX * NX; i += stride) {
        int r = i / NX, c = i % NX;
        int g = c >> 6, o = c & 63;
        const float* W = (g == 0) ? Wxr : ((g == 1) ? Wxz : Wxn);
        g_Wx[i] = W[r * 64 + o];
    }
    for (int i = blockIdx.x * blockDim.x + threadIdx.x; i < KH * NH; i += stride) {
        int r = i / NH, c = i % NH;
        int g = c >> 6, o = c & 63;
        g_Wh[i] = ((g == 0) ? Whr : Whz)[r * 64 + o];
    }
}

// ---------------- spline scatter: one thread per (edge, corner) ----------------
__global__ void scatter_kernel(const int* __restrict__ ei, const float* __restrict__ ea,
                               const float* __restrict__ x, const float* __restrict__ h) {
    int t = blockIdx.x * blockDim.x + threadIdx.x;
    if (t >= E_EDGES * 8) return;
    int e = t >> 3;
    int s = t & 7;
    int src = ei[e];
    int dst = ei[E_EDGES + e];

    float basis = 1.f;
    int idx = 0;
    const int strides[3] = {25, 5, 1};
#pragma unroll
    for (int d = 0; d < 3; d++) {
        float u = ea[e * 3 + d] * 4.0f;           // (KS-1) intervals
        int i0 = (int)floorf(u);
        i0 = i0 < 0 ? 0 : (i0 > 3 ? 3 : i0);      // clip to [0, KS-2]
        float fr = u - (float)i0;
        int b = (s >> d) & 1;
        idx += (i0 + b) * strides[d];
        basis *= b ? fr : (1.0f - fr);
    }

    if (s == 0) atomicAdd(&g_deg[dst], 1.0f);
    if (basis == 0.0f) return;

    const float4* x4 = reinterpret_cast<const float4*>(x) + src * (CIN / 4);
    float* txb = g_Tx + ((long long)dst * KK + idx) * CIN;
#pragma unroll
    for (int c = 0; c < CIN / 4; c++) {
        float4 v = x4[c];
        red_add_f4(txb + 4 * c, basis * v.x, basis * v.y, basis * v.z, basis * v.w);
    }
    const float4* h4 = reinterpret_cast<const float4*>(h) + src * (CHID / 4);
    float* thb = g_Th + ((long long)dst * KK + idx) * CHID;
#pragma unroll
    for (int c = 0; c < CHID / 4; c++) {
        float4 v = h4[c];
        red_add_f4(thb + 4 * c, basis * v.x, basis * v.y, basis * v.z, basis * v.w);
    }
}

// ---------------- fp32 tiled GEMM: C[M,NN] = A[M,KD] @ B[KD,NN] ----------------
// WHICH=0: Tx @ Wx -> convx (NN=192, KD=4000); WHICH=1: Th @ Wh -> convh (NN=128, KD=8000)
template <int WHICH>
__global__ void gemm_kernel() {
    constexpr int NN = (WHICH == 0) ? NX : NH;
    constexpr int KD = (WHICH == 0) ? KX : KH;
    constexpr int M  = N_NODES;
    constexpr int BM = 64, BN = 64, BK = 16, TM = 8, TN = 4;
    constexpr int THREADS = (BM / TM) * (BN / TN);   // 128

    const float* __restrict__ A = (WHICH == 0) ? g_Tx : g_Th;
    const float* __restrict__ B = (WHICH == 0) ? g_Wx : g_Wh;
    float* __restrict__ C       = (WHICH == 0) ? g_convx : g_convh;

    __shared__ float As[BK][BM];
    __shared__ float Bs[BK][BN];

    const int tid = threadIdx.x;
    const int tx = tid % (BN / TN);   // 16
    const int ty = tid / (BN / TN);   // 8
    const int m0 = blockIdx.y * BM;
    const int n0 = blockIdx.x * BN;

    float acc[TM][TN] = {};

    for (int k0 = 0; k0 < KD; k0 += BK) {
#pragma unroll
        for (int i = tid; i < BM * BK; i += THREADS) {
            int m = i / BK, k = i % BK;
            float v = 0.f;
            if (m0 + m < M) v = A[(m0 + m) * KD + k0 + k];
            As[k][m] = v;
        }
#pragma unroll
        for (int i = tid; i < BK * BN; i += THREADS) {
            int k = i / BN, n = i % BN;
            Bs[k][n] = B[(k0 + k) * NN + n0 + n];
        }
        __syncthreads();
#pragma unroll
        for (int k = 0; k < BK; k++) {
            float4 a0 = *reinterpret_cast<const float4*>(&As[k][ty * TM]);
            float4 a1 = *reinterpret_cast<const float4*>(&As[k][ty * TM + 4]);
            float4 bb = *reinterpret_cast<const float4*>(&Bs[k][tx * TN]);
            float a[TM] = {a0.x, a0.y, a0.z, a0.w, a1.x, a1.y, a1.z, a1.w};
            float b[TN] = {bb.x, bb.y, bb.z, bb.w};
#pragma unroll
            for (int i = 0; i < TM; i++)
#pragma unroll
                for (int j = 0; j < TN; j++) acc[i][j] += a[i] * b[j];
        }
        __syncthreads();
    }

#pragma unroll
    for (int i = 0; i < TM; i++) {
        int m = m0 + ty * TM + i;
        if (m < M) {
#pragma unroll
            for (int j = 0; j < TN; j++)
                C[m * NN + n0 + tx * TN + j] = acc[i][j];
        }
    }
}

// ---------------- fused epilogue: deg-div + root GEMVs + bias + GRU gates ----------------
__global__ void final_kernel(const float* __restrict__ x, const float* __restrict__ h,
                             const float* __restrict__ root_xr, const float* __restrict__ b_xr,
                             const float* __restrict__ root_hr, const float* __restrict__ b_hr,
                             const float* __restrict__ root_xz, const float* __restrict__ b_xz,
                             const float* __restrict__ root_hz, const float* __restrict__ b_hz,
                             const float* __restrict__ root_xn, const float* __restrict__ b_xn,
                             float* __restrict__ out) {
    int n = blockIdx.x;
    int o = threadIdx.x;           // 64 threads: one output channel each
    __shared__ float xv[CIN];
    __shared__ float hv[CHID];
    if (o < CIN) xv[o] = x[n * CIN + o];
    hv[o] = h[n * CHID + o];
    __syncthreads();

    float inv = 1.0f / fmaxf(g_deg[n], 1.0f);
    float cxr = g_convx[n * NX + o] * inv;
    float cxz = g_convx[n * NX + 64 + o] * inv;
    float cxn = g_convx[n * NX + 128 + o] * inv;
    float chr_ = g_convh[n * NH + o] * inv;
    float chz = g_convh[n * NH + 64 + o] * inv;

    float rxr = 0.f, rxz = 0.f, rxn = 0.f;
#pragma unroll
    for (int i = 0; i < CIN; i++) {
        float xi = xv[i];
        rxr += xi * root_xr[i * 64 + o];
        rxz += xi * root_xz[i * 64 + o];
        rxn += xi * root_xn[i * 64 + o];
    }
    float rhr = 0.f, rhz = 0.f;
#pragma unroll
    for (int i = 0; i < CHID; i++) {
        float hi = hv[i];
        rhr += hi * root_hr[i * 64 + o];
        rhz += hi * root_hz[i * 64 + o];
    }

    float hr_out = chr_ + rhr + b_hr[o];                       // full spline_conv(hidden; hr)
    float r = 1.f / (1.f + expf(-(cxr + rxr + b_xr[o] + hr_out)));
    float z = 1.f / (1.f + expf(-(cxz + rxz + b_xz[o] + chz + rhz + b_hz[o])));
    float ng = tanhf(cxn + rxn + b_xn[o] + r * hr_out);        // n-gate reuses hr_out (faithful)
    out[n * CHID + o] = (1.f - z) * ng + z * hv[o];
}

// ---------------- launch ----------------
extern "C" void kernel_launch(void* const* d_in, const int* in_sizes, int n_in,
                              void* d_out, int out_size) {
    const float* x       = (const float*)d_in[0];
    const float* h       = (const float*)d_in[1];
    const int*   ei      = (const int*)  d_in[2];
    const float* ea      = (const float*)d_in[3];
    const float* W_xr    = (const float*)d_in[4];
    const float* root_xr = (const float*)d_in[5];
    const float* b_xr    = (const float*)d_in[6];
    const float* W_hr    = (const float*)d_in[7];
    const float* root_hr = (const float*)d_in[8];
    const float* b_hr    = (const float*)d_in[9];
    const float* W_xz    = (const float*)d_in[10];
    const float* root_xz = (const float*)d_in[11];
    const float* b_xz    = (const float*)d_in[12];
    const float* W_hz    = (const float*)d_in[13];
    const float* root_hz = (const float*)d_in[14];
    const float* b_hz    = (const float*)d_in[15];
    const float* W_xn    = (const float*)d_in[16];
    const float* root_xn = (const float*)d_in[17];
    const float* b_xn    = (const float*)d_in[18];
    // d_in[19..21] = W_hn / root_hn / b_hn : dead in the reference forward.
    float* out = (float*)d_out;

    zero_kernel<<<8192, 256>>>();
    pack_kernel<<<2048, 256>>>(W_xr, W_xz, W_xn, W_hr, W_hz);
    scatter_kernel<<<(E_EDGES * 8 + 255) / 256, 256>>>(ei, ea, x, h);

    dim3 gx(NX / 64, (N_NODES + 63) / 64);   // 3 x 94
    gemm_kernel<0><<<gx, 128>>>();
    dim3 gh(NH / 64, (N_NODES + 63) / 64);   // 2 x 94
    gemm_kernel<1><<<gh, 128>>>();

    final_kernel<<<N_NODES, CHID>>>(x, h,
                                    root_xr, b_xr, root_hr, b_hr,
                                    root_xz, b_xz, root_hz, b_hz,
                                    root_xn, b_xn, out);
}

// round 5
// speedup vs baseline: 6.7743x; 6.7743x over previous
#include <cuda_runtime.h>
#include <math.h>
#include <stdint.h>

// ---------------- problem constants ----------------
#define N_NODES 6000
#define E_EDGES 192000
#define CIN     32
#define CHID    64
#define KK      125
#define NX      192          // 3 gates * 64 (xr | xz | xn)
#define NH      128          // 2 gates * 64 (hr | hz)
#define KX      (KK * CIN)   // 4000
#define KH      (KK * CHID)  // 8000
#define MT      47           // ceil(6000/128) M tiles

// GEMM tiling
#define BM 128
#define BN 64
#define BK 32
#define ASTRIDE 36                    // padded floats per smem row
#define A_BUF_FLOATS (BM * ASTRIDE)   // 4608
#define B_BUF_FLOATS (BN * ASTRIDE)   // 2304
#define SMEM_FLOATS (2 * A_BUF_FLOATS + 2 * B_BUF_FLOATS)   // 13824 floats = 55296 B

// ---------------- static device scratch ----------------
__device__ __align__(1024) float g_Tx[N_NODES * KK * CIN];    //  96 MB
__device__ __align__(1024) float g_Th[N_NODES * KK * CHID];   // 192 MB
__device__ float g_deg[N_NODES];
__device__ float g_convx[N_NODES * NX];
__device__ float g_convh[N_NODES * NH];
__device__ __align__(1024) float g_Wx[NX * KX];               // transposed [N,K]
__device__ __align__(1024) float g_Wh[NH * KH];               // transposed [N,K]

// ---------------- PTX helpers (all plain sm_80/sm_90 — no 'a'-gated features) ----------------
__device__ __forceinline__ uint32_t smem_u32(const void* p) {
    uint32_t a;
    asm("{ .reg .u64 t; cvta.to.shared.u64 t, %1; cvt.u32.u64 %0, t; }" : "=r"(a) : "l"(p));
    return a;
}
__device__ __forceinline__ void red_add_f4(float* p, float a, float b, float c, float d) {
    asm volatile("red.global.add.v4.f32 [%0], {%1,%2,%3,%4};"
                 :: "l"(p), "f"(a), "f"(b), "f"(c), "f"(d) : "memory");
}
__device__ __forceinline__ void cp_async16(uint32_t dst, const void* src, int sz) {
    asm volatile("cp.async.cg.shared.global [%0], [%1], 16, %2;"
                 :: "r"(dst), "l"(src), "r"(sz) : "memory");
}
__device__ __forceinline__ void cp_commit() { asm volatile("cp.async.commit_group;" ::: "memory"); }
__device__ __forceinline__ void cp_wait0()  { asm volatile("cp.async.wait_group 0;" ::: "memory"); }

__device__ __forceinline__ uint32_t f2tf(float f) {
    uint32_t u;
    asm("cvt.rna.tf32.f32 %0, %1;" : "=r"(u) : "f"(f));
    return u;
}
__device__ __forceinline__ void mma_tf32(float* c, const uint32_t* a, const uint32_t* b) {
    asm volatile("mma.sync.aligned.m16n8k8.row.col.f32.tf32.tf32.f32 "
                 "{%0,%1,%2,%3}, {%4,%5,%6,%7}, {%8,%9}, {%0,%1,%2,%3};"
                 : "+f"(c[0]), "+f"(c[1]), "+f"(c[2]), "+f"(c[3])
                 : "r"(a[0]), "r"(a[1]), "r"(a[2]), "r"(a[3]), "r"(b[0]), "r"(b[1]));
}

// ---------------- pack transposed weights: g_W*[n, k] = W[k, n] ----------------
__global__ void pack_kernel(const float* __restrict__ Wxr, const float* __restrict__ Wxz,
                            const float* __restrict__ Wxn, const float* __restrict__ Whr,
                            const float* __restrict__ Whz) {
    int stride = gridDim.x * blockDim.x;
    for (int i = blockIdx.x * blockDim.x + threadIdx.x; i < NX * KX; i += stride) {
        int n = i / KX, k = i % KX;
        int g = n >> 6, o = n & 63;
        const float* W = (g == 0) ? Wxr : ((g == 1) ? Wxz : Wxn);
        g_Wx[i] = W[k * 64 + o];
    }
    for (int i = blockIdx.x * blockDim.x + threadIdx.x; i < NH * KH; i += stride) {
        int n = i / KH, k = i % KH;
        int g = n >> 6, o = n & 63;
        g_Wh[i] = ((g == 0) ? Whr : Whz)[k * 64 + o];
    }
}

// ---------------- spline scatter: one thread per (edge, corner) ----------------
__global__ void scatter_kernel(const int* __restrict__ ei, const float* __restrict__ ea,
                               const float* __restrict__ x, const float* __restrict__ h) {
    int t = blockIdx.x * blockDim.x + threadIdx.x;
    if (t >= E_EDGES * 8) return;
    int e = t >> 3;
    int s = t & 7;
    int src = ei[e];
    int dst = ei[E_EDGES + e];

    float basis = 1.f;
    int idx = 0;
    const int strides[3] = {25, 5, 1};
#pragma unroll
    for (int d = 0; d < 3; d++) {
        float u = ea[e * 3 + d] * 4.0f;
        int i0 = (int)floorf(u);
        i0 = i0 < 0 ? 0 : (i0 > 3 ? 3 : i0);
        float fr = u - (float)i0;
        int b = (s >> d) & 1;
        idx += (i0 + b) * strides[d];
        basis *= b ? fr : (1.0f - fr);
    }

    if (s == 0) atomicAdd(&g_deg[dst], 1.0f);
    if (basis == 0.0f) return;

    const float4* x4 = reinterpret_cast<const float4*>(x) + src * (CIN / 4);
    float* txb = g_Tx + ((long long)dst * KK + idx) * CIN;
#pragma unroll
    for (int c = 0; c < CIN / 4; c++) {
        float4 v = x4[c];
        red_add_f4(txb + 4 * c, basis * v.x, basis * v.y, basis * v.z, basis * v.w);
    }
    const float4* h4 = reinterpret_cast<const float4*>(h) + src * (CHID / 4);
    float* thb = g_Th + ((long long)dst * KK + idx) * CHID;
#pragma unroll
    for (int c = 0; c < CHID / 4; c++) {
        float4 v = h4[c];
        red_add_f4(thb + 4 * c, basis * v.x, basis * v.y, basis * v.z, basis * v.w);
    }
}

// ---------------- fused tensor-core GEMM via mma.sync tf32 ----------------
// C[M, NB] = A[M, KD] @ Wt[NB, KD]^T. Blocks 0..140: gemm0 (Tx@Wx), 141..234: gemm1 (Th@Wh).
__global__ void __launch_bounds__(256, 2) gemm_mma() {
    extern __shared__ float smf[];
    const int tid = threadIdx.x;
    const int wid = tid >> 5, lane = tid & 31;
    const int wm = wid & 3, wn = wid >> 2;          // warp grid 4 (M) x 2 (N)

    int bx = blockIdx.x;
    const int which = (bx >= MT * 3) ? 1 : 0;
    if (which) bx -= MT * 3;
    const int ntiles = which ? 2 : 3;
    const int mtile = bx / ntiles;
    const int ntile = bx % ntiles;
    const int NB = which ? NH : NX;
    const int KD = which ? KH : KX;
    const int NIT = KD / BK;                        // 125 or 250
    const int m0 = mtile * BM;
    const int n0 = ntile * BN;
    const float* __restrict__ A = which ? g_Th : g_Tx;
    const float* __restrict__ Bw = which ? g_Wh : g_Wx;
    float* __restrict__ C = which ? g_convh : g_convx;

    const uint32_t sbase = smem_u32(smf);
    // layout: A0 | A1 | B0 | B1  (float counts)
    const uint32_t aoff[2] = {0u, (uint32_t)A_BUF_FLOATS * 4u};
    const uint32_t boff[2] = {(uint32_t)(2 * A_BUF_FLOATS) * 4u,
                              (uint32_t)(2 * A_BUF_FLOATS + B_BUF_FLOATS) * 4u};

    // cp.async load of one BK slice into buffer `buf` at k offset k0
    auto load_tiles = [&](int k0, int buf) {
        // A: 128 rows x 8 chunks of 16B = 1024 chunks, 4 per thread
#pragma unroll
        for (int it = 0; it < 4; it++) {
            int chunk = tid + it * 256;
            int row = chunk >> 3, c = chunk & 7;
            int gr = m0 + row;
            uint32_t dst = sbase + aoff[buf] + (uint32_t)(row * ASTRIDE * 4 + c * 16);
            const float* src = A + (long long)gr * KD + k0 + c * 4;
            cp_async16(dst, src, (gr < N_NODES) ? 16 : 0);
        }
        // B: 64 rows x 8 chunks = 512 chunks, 2 per thread
#pragma unroll
        for (int it = 0; it < 2; it++) {
            int chunk = tid + it * 256;
            int row = chunk >> 3, c = chunk & 7;
            uint32_t dst = sbase + boff[buf] + (uint32_t)(row * ASTRIDE * 4 + c * 16);
            const float* src = Bw + (long long)(n0 + row) * KD + k0 + c * 4;
            cp_async16(dst, src, 16);
        }
        cp_commit();
    };

    float acc[2][4][4] = {};

    load_tiles(0, 0);
    cp_wait0();
    __syncthreads();

    int cur = 0;
    for (int kt = 0; kt < NIT; kt++) {
        if (kt + 1 < NIT) load_tiles((kt + 1) * BK, cur ^ 1);

        const float* As = smf + (aoff[cur] >> 2);
        const float* Bs = smf + (boff[cur] >> 2);
        const int r0 = wm * 32 + (lane >> 2);
        const int nrow0 = wn * 32 + (lane >> 2);
        const int kc = lane & 3;
#pragma unroll
        for (int ks = 0; ks < 4; ks++) {
            const int k8 = ks * 8;
            uint32_t a[2][4];
#pragma unroll
            for (int mt = 0; mt < 2; mt++) {
                int r = r0 + mt * 16;
                a[mt][0] = f2tf(As[r * ASTRIDE + k8 + kc]);
                a[mt][1] = f2tf(As[(r + 8) * ASTRIDE + k8 + kc]);
                a[mt][2] = f2tf(As[r * ASTRIDE + k8 + kc + 4]);
                a[mt][3] = f2tf(As[(r + 8) * ASTRIDE + k8 + kc + 4]);
            }
            uint32_t bf[4][2];
#pragma unroll
            for (int nt = 0; nt < 4; nt++) {
                int nr = nrow0 + nt * 8;
                bf[nt][0] = f2tf(Bs[nr * ASTRIDE + k8 + kc]);
                bf[nt][1] = f2tf(Bs[nr * ASTRIDE + k8 + kc + 4]);
            }
#pragma unroll
            for (int mt = 0; mt < 2; mt++)
#pragma unroll
                for (int nt = 0; nt < 4; nt++)
                    mma_tf32(acc[mt][nt], a[mt], bf[nt]);
        }

        if (kt + 1 < NIT) cp_wait0();
        __syncthreads();
        cur ^= 1;
    }

    // epilogue: fragment layout -> global C
#pragma unroll
    for (int mt = 0; mt < 2; mt++) {
        int r = m0 + wm * 32 + mt * 16 + (lane >> 2);
#pragma unroll
        for (int nt = 0; nt < 4; nt++) {
            int col = n0 + wn * 32 + nt * 8 + (lane & 3) * 2;
            if (r < N_NODES)
                *reinterpret_cast<float2*>(&C[r * NB + col]) =
                    make_float2(acc[mt][nt][0], acc[mt][nt][1]);
            if (r + 8 < N_NODES)
                *reinterpret_cast<float2*>(&C[(r + 8) * NB + col]) =
                    make_float2(acc[mt][nt][2], acc[mt][nt][3]);
        }
    }
}

// ---------------- fused epilogue: deg-div + root GEMVs + bias + GRU gates ----------------
__global__ void final_kernel(const float* __restrict__ x, const float* __restrict__ h,
                             const float* __restrict__ root_xr, const float* __restrict__ b_xr,
                             const float* __restrict__ root_hr, const float* __restrict__ b_hr,
                             const float* __restrict__ root_xz, const float* __restrict__ b_xz,
                             const float* __restrict__ root_hz, const float* __restrict__ b_hz,
                             const float* __restrict__ root_xn, const float* __restrict__ b_xn,
                             float* __restrict__ out) {
    int n = blockIdx.x;
    int o = threadIdx.x;
    __shared__ float xv[CIN];
    __shared__ float hv[CHID];
    if (o < CIN) xv[o] = x[n * CIN + o];
    hv[o] = h[n * CHID + o];
    __syncthreads();

    float inv = 1.0f / fmaxf(g_deg[n], 1.0f);
    float cxr = g_convx[n * NX + o] * inv;
    float cxz = g_convx[n * NX + 64 + o] * inv;
    float cxn = g_convx[n * NX + 128 + o] * inv;
    float chr_ = g_convh[n * NH + o] * inv;
    float chz = g_convh[n * NH + 64 + o] * inv;

    float rxr = 0.f, rxz = 0.f, rxn = 0.f;
#pragma unroll
    for (int i = 0; i < CIN; i++) {
        float xi = xv[i];
        rxr += xi * root_xr[i * 64 + o];
        rxz += xi * root_xz[i * 64 + o];
        rxn += xi * root_xn[i * 64 + o];
    }
    float rhr = 0.f, rhz = 0.f;
#pragma unroll
    for (int i = 0; i < CHID; i++) {
        float hi = hv[i];
        rhr += hi * root_hr[i * 64 + o];
        rhz += hi * root_hz[i * 64 + o];
    }

    float hr_out = chr_ + rhr + b_hr[o];
    float r = 1.f / (1.f + expf(-(cxr + rxr + b_xr[o] + hr_out)));
    float z = 1.f / (1.f + expf(-(cxz + rxz + b_xz[o] + chz + rhz + b_hz[o])));
    float ng = tanhf(cxn + rxn + b_xn[o] + r * hr_out);
    out[n * CHID + o] = (1.f - z) * ng + z * hv[o];
}

// ---------------- host launch ----------------
extern "C" void kernel_launch(void* const* d_in, const int* in_sizes, int n_in,
                              void* d_out, int out_size) {
    const float* x       = (const float*)d_in[0];
    const float* h       = (const float*)d_in[1];
    const int*   ei      = (const int*)  d_in[2];
    const float* ea      = (const float*)d_in[3];
    const float* W_xr    = (const float*)d_in[4];
    const float* root_xr = (const float*)d_in[5];
    const float* b_xr    = (const float*)d_in[6];
    const float* W_hr    = (const float*)d_in[7];
    const float* root_hr = (const float*)d_in[8];
    const float* b_hr    = (const float*)d_in[9];
    const float* W_xz    = (const float*)d_in[10];
    const float* root_xz = (const float*)d_in[11];
    const float* b_xz    = (const float*)d_in[12];
    const float* W_hz    = (const float*)d_in[13];
    const float* root_hz = (const float*)d_in[14];
    const float* b_hz    = (const float*)d_in[15];
    const float* W_xn    = (const float*)d_in[16];
    const float* root_xn = (const float*)d_in[17];
    const float* b_xn    = (const float*)d_in[18];
    float* out = (float*)d_out;

    void *pTx, *pTh, *pDeg;
    cudaGetSymbolAddress(&pTx, g_Tx);
    cudaGetSymbolAddress(&pTh, g_Th);
    cudaGetSymbolAddress(&pDeg, g_deg);

    cudaMemsetAsync(pTx, 0, (size_t)N_NODES * KK * CIN * 4);
    cudaMemsetAsync(pTh, 0, (size_t)N_NODES * KK * CHID * 4);
    cudaMemsetAsync(pDeg, 0, N_NODES * 4);

    pack_kernel<<<2048, 256>>>(W_xr, W_xz, W_xn, W_hr, W_hz);
    scatter_kernel<<<(E_EDGES * 8 + 255) / 256, 256>>>(ei, ea, x, h);

    cudaFuncSetAttribute(gemm_mma, cudaFuncAttributeMaxDynamicSharedMemorySize,
                         SMEM_FLOATS * 4);
    gemm_mma<<<MT * 3 + MT * 2, 256, SMEM_FLOATS * 4>>>();

    final_kernel<<<N_NODES, CHID>>>(x, h,
                                    root_xr, b_xr, root_hr, b_hr,
                                    root_xz, b_xz, root_hz, b_hz,
                                    root_xn, b_xn, out);
}

// round 9
// speedup vs baseline: 7.2250x; 1.0665x over previous
#include <cuda_runtime.h>
#include <math.h>
#include <stdint.h>

// ---------------- problem constants ----------------
#define N_NODES 6000
#define E_EDGES 192000
#define CIN     32
#define CHID    64
#define KK      125
#define NX      192          // 3 gates * 64 (xr | xz | xn)
#define NH      128          // 2 gates * 64 (hr | hz)
#define KX      (KK * CIN)   // 4000
#define KH      (KK * CHID)  // 8000
#define MT      47           // ceil(6000/128) M tiles

// GEMM tiling
#define BM 128
#define BK 32
#define ASTRIDE 36                    // padded floats per smem row

// ---------------- static device scratch ----------------
__device__ __align__(1024) float g_Tx[(size_t)N_NODES * KX];    //  96 MB
__device__ __align__(1024) float g_Th[(size_t)N_NODES * KH];    // 192 MB
__device__ float g_convx[N_NODES * NX];
__device__ float g_convh[N_NODES * NH];
__device__ __align__(1024) float g_Wx[NX * KX];               // transposed [N,K]
__device__ __align__(1024) float g_Wh[NH * KH];               // transposed [N,K]
__device__ int g_hist[N_NODES];       // edges per dst (= degree)
__device__ int g_cur[N_NODES];
__device__ int g_off[N_NODES + 1];
__device__ int g_sorted[E_EDGES];

// ---------------- PTX helpers (plain sm_80/90 — nothing 'a'-gated) ----------------
__device__ __forceinline__ uint32_t smem_u32(const void* p) {
    uint32_t a;
    asm("{ .reg .u64 t; cvta.to.shared.u64 t, %1; cvt.u32.u64 %0, t; }" : "=r"(a) : "l"(p));
    return a;
}
__device__ __forceinline__ void cp_async16(uint32_t dst, const void* src, int sz) {
    asm volatile("cp.async.cg.shared.global [%0], [%1], 16, %2;"
                 :: "r"(dst), "l"(src), "r"(sz) : "memory");
}
__device__ __forceinline__ void cp_commit() { asm volatile("cp.async.commit_group;" ::: "memory"); }
__device__ __forceinline__ void cp_wait0()  { asm volatile("cp.async.wait_group 0;" ::: "memory"); }

__device__ __forceinline__ uint32_t f2tf(float f) {
    uint32_t u;
    asm("cvt.rna.tf32.f32 %0, %1;" : "=r"(u) : "f"(f));
    return u;
}
__device__ __forceinline__ void mma_tf32(float* c, const uint32_t* a, const uint32_t* b) {
    asm volatile("mma.sync.aligned.m16n8k8.row.col.f32.tf32.tf32.f32 "
                 "{%0,%1,%2,%3}, {%4,%5,%6,%7}, {%8,%9}, {%0,%1,%2,%3};"
                 : "+f"(c[0]), "+f"(c[1]), "+f"(c[2]), "+f"(c[3])
                 : "r"(a[0]), "r"(a[1]), "r"(a[2]), "r"(a[3]), "r"(b[0]), "r"(b[1]));
}

// ---------------- counting sort of edges by dst ----------------
__global__ void hist_kernel(const int* __restrict__ ei) {
    int e = blockIdx.x * blockDim.x + threadIdx.x;
    if (e < E_EDGES) atomicAdd(&g_hist[ei[E_EDGES + e]], 1);
}

__global__ void prefix_kernel() {
    __shared__ int part[1024];
    int tid = threadIdx.x;
    int base = tid * 6;
    int loc[6];
    int s = 0;
#pragma unroll
    for (int i = 0; i < 6; i++) {
        int v = (base + i < N_NODES) ? g_hist[base + i] : 0;
        loc[i] = s; s += v;
    }
    part[tid] = s;
    __syncthreads();
    for (int d = 1; d < 1024; d <<= 1) {
        int v = 0;
        if (tid >= d) v = part[tid - d];
        __syncthreads();
        if (tid >= d) part[tid] += v;
        __syncthreads();
    }
    int excl = (tid == 0) ? 0 : part[tid - 1];
#pragma unroll
    for (int i = 0; i < 6; i++)
        if (base + i < N_NODES) g_off[base + i] = excl + loc[i];
    if (tid == 1023) g_off[N_NODES] = part[1023];
}

__global__ void sort_kernel(const int* __restrict__ ei) {
    int e = blockIdx.x * blockDim.x + threadIdx.x;
    if (e < E_EDGES) {
        int d = ei[E_EDGES + e];
        int p = atomicAdd(&g_cur[d], 1);
        g_sorted[g_off[d] + p] = e;
    }
}

// ---------------- pack transposed weights: g_W*[n, k] = W[k, n] ----------------
__global__ void pack_kernel(const float* __restrict__ Wxr, const float* __restrict__ Wxz,
                            const float* __restrict__ Wxn, const float* __restrict__ Whr,
                            const float* __restrict__ Whz) {
    int stride = gridDim.x * blockDim.x;
    for (int i = blockIdx.x * blockDim.x + threadIdx.x; i < NX * KX; i += stride) {
        int n = i / KX, k = i % KX;
        int g = n >> 6, o = n & 63;
        const float* W = (g == 0) ? Wxr : ((g == 1) ? Wxz : Wxn);
        g_Wx[i] = W[k * 64 + o];
    }
    for (int i = blockIdx.x * blockDim.x + threadIdx.x; i < NH * KH; i += stride) {
        int n = i / KH, k = i % KH;
        int g = n >> 6, o = n & 63;
        g_Wh[i] = ((g == 0) ? Whr : Whz)[k * 64 + o];
    }
}

// ---------------- per-dst accumulation: NO global atomics, dense write-out ----------------
// One block per dst. smem T row [125][96] (x ch 0..31, h ch 32..95), stride 97 (bank skew).
// Warp w owns channels [w*12, w*12+12): disjoint across warps -> no races.
// Within a warp: lane = (corner, cl); the 8 corners of one edge have distinct idx -> distinct addrs.
__global__ void __launch_bounds__(256) accum_kernel(const int* __restrict__ ei,
                                                    const float* __restrict__ ea,
                                                    const float* __restrict__ x,
                                                    const float* __restrict__ h) {
    __shared__ float sT[125 * 97];    // 48500 B
    const int tid = threadIdx.x;
    const int dst = blockIdx.x;
    for (int i = tid; i < 125 * 97; i += 256) sT[i] = 0.f;
    __syncthreads();

    const int wid = tid >> 5, lane = tid & 31;
    const int corner = lane >> 2, cl = lane & 3;
    const int chb = wid * 12 + cl;
    const int b0 = corner & 1, b1 = (corner >> 1) & 1, b2 = (corner >> 2) & 1;

    const int e0 = g_off[dst], e1 = g_off[dst + 1];
    for (int j = e0; j < e1; j++) {
        int e = g_sorted[j];
        int src = ei[e];
        float u0 = ea[3 * e] * 4.f, u1 = ea[3 * e + 1] * 4.f, u2 = ea[3 * e + 2] * 4.f;
        int i0 = min(max((int)floorf(u0), 0), 3);
        int i1 = min(max((int)floorf(u1), 0), 3);
        int i2 = min(max((int)floorf(u2), 0), 3);
        float f0 = u0 - (float)i0, f1 = u1 - (float)i1, f2 = u2 - (float)i2;
        int idx = (i0 + b0) * 25 + (i1 + b1) * 5 + (i2 + b2);
        float basis = (b0 ? f0 : 1.f - f0) * (b1 ? f1 : 1.f - f1) * (b2 ? f2 : 1.f - f2);
        float* row = sT + idx * 97;
#pragma unroll
        for (int t = 0; t < 3; t++) {
            int ch = chb + 4 * t;
            float v = (ch < 32) ? x[src * CIN + ch] : h[src * CHID + (ch - 32)];
            row[ch] += basis * v;
        }
    }
    __syncthreads();

    // dense write-out (replaces memset + atomics)
    const long long o = (long long)dst;
    for (int i = tid; i < KX; i += 256)
        g_Tx[o * KX + i] = sT[(i >> 5) * 97 + (i & 31)];
    for (int i = tid; i < KH; i += 256)
        g_Th[o * KH + i] = sT[(i >> 6) * 97 + 32 + (i & 63)];
}

// ---------------- tensor-core GEMM via mma.sync tf32, full-N CTAs (A read once) ----------------
template <int WHICH>
__device__ __forceinline__ void gemm_body(float* smf, int mtile) {
    constexpr int NB  = WHICH ? NH : NX;
    constexpr int KD  = WHICH ? KH : KX;
    constexpr int NIT = KD / BK;          // 250 / 125
    constexpr int WN  = NB / 2;           // 64 / 96
    constexpr int NT  = WN / 8;           // 8 / 12
    constexpr int A_FL = BM * ASTRIDE;    // 4608
    constexpr int B_FL = NB * ASTRIDE;

    const int tid = threadIdx.x;
    const int wid = tid >> 5, lane = tid & 31;
    const int wm = wid & 3, wn = wid >> 2;
    const int m0 = mtile * BM;
    const float* __restrict__ A  = WHICH ? g_Th : g_Tx;
    const float* __restrict__ Bw = WHICH ? g_Wh : g_Wx;
    float* __restrict__ C        = WHICH ? g_convh : g_convx;

    const uint32_t sbase = smem_u32(smf);
    const uint32_t aoff[2] = {0u, (uint32_t)A_FL * 4u};
    const uint32_t boff[2] = {(uint32_t)(2 * A_FL) * 4u, (uint32_t)(2 * A_FL + B_FL) * 4u};

    auto load_tiles = [&](int k0, int buf) {
#pragma unroll
        for (int it = 0; it < 4; it++) {                    // A: 1024 chunks
            int chunk = tid + it * 256;
            int row = chunk >> 3, c = chunk & 7;
            int gr = m0 + row;
            cp_async16(sbase + aoff[buf] + (uint32_t)(row * ASTRIDE * 4 + c * 16),
                       A + (long long)gr * KD + k0 + c * 4, (gr < N_NODES) ? 16 : 0);
        }
#pragma unroll
        for (int it = 0; it < NB * 8 / 256; it++) {         // B: NB*8 chunks
            int chunk = tid + it * 256;
            int row = chunk >> 3, c = chunk & 7;
            cp_async16(sbase + boff[buf] + (uint32_t)(row * ASTRIDE * 4 + c * 16),
                       Bw + (long long)row * KD + k0 + c * 4, 16);
        }
        cp_commit();
    };

    float acc[2][NT][4] = {};

    load_tiles(0, 0);
    cp_wait0();
    __syncthreads();

    int cur = 0;
    for (int kt = 0; kt < NIT; kt++) {
        if (kt + 1 < NIT) load_tiles((kt + 1) * BK, cur ^ 1);

        const float* As = smf + (aoff[cur] >> 2);
        const float* Bs = smf + (boff[cur] >> 2);
        const int r0  = wm * 32 + (lane >> 2);
        const int n0r = wn * WN + (lane >> 2);
        const int kc  = lane & 3;
#pragma unroll
        for (int ks = 0; ks < 4; ks++) {
            const int k8 = ks * 8;
            uint32_t a[2][4];
#pragma unroll
            for (int mt = 0; mt < 2; mt++) {
                int r = r0 + mt * 16;
                a[mt][0] = f2tf(As[r * ASTRIDE + k8 + kc]);
                a[mt][1] = f2tf(As[(r + 8) * ASTRIDE + k8 + kc]);
                a[mt][2] = f2tf(As[r * ASTRIDE + k8 + kc + 4]);
                a[mt][3] = f2tf(As[(r + 8) * ASTRIDE + k8 + kc + 4]);
            }
            uint32_t bf[NT][2];
#pragma unroll
            for (int nt = 0; nt < NT; nt++) {
                int nr = n0r + nt * 8;
                bf[nt][0] = f2tf(Bs[nr * ASTRIDE + k8 + kc]);
                bf[nt][1] = f2tf(Bs[nr * ASTRIDE + k8 + kc + 4]);
            }
#pragma unroll
            for (int mt = 0; mt < 2; mt++)
#pragma unroll
                for (int nt = 0; nt < NT; nt++)
                    mma_tf32(acc[mt][nt], a[mt], bf[nt]);
        }

        if (kt + 1 < NIT) cp_wait0();
        __syncthreads();
        cur ^= 1;
    }

#pragma unroll
    for (int mt = 0; mt < 2; mt++) {
        int r = m0 + wm * 32 + mt * 16 + (lane >> 2);
#pragma unroll
        for (int nt = 0; nt < NT; nt++) {
            int col = wn * WN + nt * 8 + (lane & 3) * 2;
            if (r < N_NODES)
                *reinterpret_cast<float2*>(&C[(long long)r * NB + col]) =
                    make_float2(acc[mt][nt][0], acc[mt][nt][1]);
            if (r + 8 < N_NODES)
                *reinterpret_cast<float2*>(&C[(long long)(r + 8) * NB + col]) =
                    make_float2(acc[mt][nt][2], acc[mt][nt][3]);
        }
    }
}

__global__ void __launch_bounds__(256, 1) gemm_mma() {
    extern __shared__ float smf[];
    if (blockIdx.x < MT) gemm_body<0>(smf, blockIdx.x);
    else                 gemm_body<1>(smf, blockIdx.x - MT);
}
#define GEMM_SMEM ((2 * BM * ASTRIDE + 2 * NX * ASTRIDE) * 4)   // 92160 B

// ---------------- fused epilogue: roots cached in smem, 16 nodes/block ----------------
#define FN_PER_BLK 16
#define FS_FLOATS (14336 + 5 * 64)
__global__ void __launch_bounds__(256) final_kernel(
        const float* __restrict__ x, const float* __restrict__ h,
        const float* __restrict__ root_xr, const float* __restrict__ b_xr,
        const float* __restrict__ root_hr, const float* __restrict__ b_hr,
        const float* __restrict__ root_xz, const float* __restrict__ b_xz,
        const float* __restrict__ root_hz, const float* __restrict__ b_hz,
        const float* __restrict__ root_xn, const float* __restrict__ b_xn,
        float* __restrict__ out) {
    extern __shared__ float fs[];
    const int tid = threadIdx.x;
    for (int i = tid; i < 2048; i += 256) {
        fs[i]        = root_xr[i];
        fs[2048 + i] = root_xz[i];
        fs[4096 + i] = root_xn[i];
    }
    for (int i = tid; i < 4096; i += 256) {
        fs[6144 + i]  = root_hr[i];
        fs[10240 + i] = root_hz[i];
    }
    if (tid < 64) {
        fs[14336 + tid] = b_xr[tid];
        fs[14400 + tid] = b_hr[tid];
        fs[14464 + tid] = b_xz[tid];
        fs[14528 + tid] = b_hz[tid];
        fs[14592 + tid] = b_xn[tid];
    }
    __syncthreads();

    const int o = tid & 63, q = tid >> 6;
    const int nb = blockIdx.x * FN_PER_BLK;
#pragma unroll
    for (int it = 0; it < FN_PER_BLK / 4; it++) {
        int n = nb + it * 4 + q;
        if (n >= N_NODES) continue;
        float inv = 1.f / fmaxf((float)g_hist[n], 1.f);
        float cxr  = g_convx[n * NX + o] * inv;
        float cxz  = g_convx[n * NX + 64 + o] * inv;
        float cxn  = g_convx[n * NX + 128 + o] * inv;
        float chr_ = g_convh[n * NH + o] * inv;
        float chz  = g_convh[n * NH + 64 + o] * inv;

        float rxr = 0.f, rxz = 0.f, rxn = 0.f;
#pragma unroll
        for (int i = 0; i < CIN; i++) {
            float xi = x[n * CIN + i];
            rxr += xi * fs[i * 64 + o];
            rxz += xi * fs[2048 + i * 64 + o];
            rxn += xi * fs[4096 + i * 64 + o];
        }
        float rhr = 0.f, rhz = 0.f;
#pragma unroll
        for (int i = 0; i < CHID; i++) {
            float hi = h[n * CHID + i];
            rhr += hi * fs[6144 + i * 64 + o];
            rhz += hi * fs[10240 + i * 64 + o];
        }

        float hr_out = chr_ + rhr + fs[14400 + o];
        float r = 1.f / (1.f + expf(-(cxr + rxr + fs[14336 + o] + hr_out)));
        float z = 1.f / (1.f + expf(-(cxz + rxz + fs[14464 + o] + chz + rhz + fs[14528 + o])));
        float ng = tanhf(cxn + rxn + fs[14592 + o] + r * hr_out);
        out[n * CHID + o] = (1.f - z) * ng + z * h[n * CHID + o];
    }
}

// ---------------- host launch ----------------
extern "C" void kernel_launch(void* const* d_in, const int* in_sizes, int n_in,
                              void* d_out, int out_size) {
    const float* x       = (const float*)d_in[0];
    const float* h       = (const float*)d_in[1];
    const int*   ei      = (const int*)  d_in[2];
    const float* ea      = (const float*)d_in[3];
    const float* W_xr    = (const float*)d_in[4];
    const float* root_xr = (const float*)d_in[5];
    const float* b_xr    = (const float*)d_in[6];
    const float* W_hr    = (const float*)d_in[7];
    const float* root_hr = (const float*)d_in[8];
    const float* b_hr    = (const float*)d_in[9];
    const float* W_xz    = (const float*)d_in[10];
    const float* root_xz = (const float*)d_in[11];
    const float* b_xz    = (const float*)d_in[12];
    const float* W_hz    = (const float*)d_in[13];
    const float* root_hz = (const float*)d_in[14];
    const float* b_hz    = (const float*)d_in[15];
    const float* W_xn    = (const float*)d_in[16];
    const float* root_xn = (const float*)d_in[17];
    const float* b_xn    = (const float*)d_in[18];
    float* out = (float*)d_out;

    void *pHist, *pCur;
    cudaGetSymbolAddress(&pHist, g_hist);
    cudaGetSymbolAddress(&pCur, g_cur);
    cudaMemsetAsync(pHist, 0, N_NODES * 4);
    cudaMemsetAsync(pCur, 0, N_NODES * 4);

    hist_kernel<<<(E_EDGES + 255) / 256, 256>>>(ei);
    prefix_kernel<<<1, 1024>>>();
    sort_kernel<<<(E_EDGES + 255) / 256, 256>>>(ei);

    pack_kernel<<<2048, 256>>>(W_xr, W_xz, W_xn, W_hr, W_hz);

    accum_kernel<<<N_NODES, 256>>>(ei, ea, x, h);

    cudaFuncSetAttribute(gemm_mma, cudaFuncAttributeMaxDynamicSharedMemorySize, GEMM_SMEM);
    gemm_mma<<<2 * MT, 256, GEMM_SMEM>>>();

    cudaFuncSetAttribute(final_kernel, cudaFuncAttributeMaxDynamicSharedMemorySize,
                         FS_FLOATS * 4);
    final_kernel<<<(N_NODES + FN_PER_BLK - 1) / FN_PER_BLK, 256, FS_FLOATS * 4>>>(
        x, h, root_xr, b_xr, root_hr, b_hr, root_xz, b_xz, root_hz, b_hz,
        root_xn, b_xn, out);
}

// round 12
// speedup vs baseline: 8.3469x; 1.1553x over previous
#include <cuda_runtime.h>
#include <math.h>
#include <stdint.h>

// ---------------- problem constants ----------------
#define N_NODES 6000
#define E_EDGES 192000
#define CIN     32
#define CHID    64
#define KK      125
#define NX      192          // 3 gates * 64 (xr | xz | xn)
#define NH      128          // 2 gates * 64 (hr | hz)
#define KX      (KK * CIN)   // 4000
#define KH      (KK * CHID)  // 8000
#define MT      47           // ceil(6000/128) M tiles

// GEMM tiling
#define BM 128
#define BK 32
#define ASTRIDE 36                    // padded floats per smem row

// ---------------- static device scratch ----------------
__device__ __align__(1024) float g_Tx[(size_t)N_NODES * KX];    //  96 MB
__device__ __align__(1024) float g_Th[(size_t)N_NODES * KH];    // 192 MB
__device__ float g_convx[N_NODES * NX];
__device__ float g_convh[N_NODES * NH];
__device__ __align__(1024) float g_Wx[NX * KX];               // transposed [N,K]
__device__ __align__(1024) float g_Wh[NH * KH];               // transposed [N,K]
__device__ int g_hist[N_NODES];       // edges per dst (= degree)
__device__ int g_cur[N_NODES];
__device__ int g_off[N_NODES + 1];
__device__ __align__(16) float4 g_rec[E_EDGES];   // sorted {src, u0, u1, u2}

// ---------------- PTX helpers (plain sm_80/90 — nothing 'a'-gated) ----------------
__device__ __forceinline__ uint32_t smem_u32(const void* p) {
    uint32_t a;
    asm("{ .reg .u64 t; cvta.to.shared.u64 t, %1; cvt.u32.u64 %0, t; }" : "=r"(a) : "l"(p));
    return a;
}
__device__ __forceinline__ void cp_async16(uint32_t dst, const void* src, int sz) {
    asm volatile("cp.async.cg.shared.global [%0], [%1], 16, %2;"
                 :: "r"(dst), "l"(src), "r"(sz) : "memory");
}
__device__ __forceinline__ void cp_commit() { asm volatile("cp.async.commit_group;" ::: "memory"); }
__device__ __forceinline__ void cp_wait0()  { asm volatile("cp.async.wait_group 0;" ::: "memory"); }

__device__ __forceinline__ uint32_t f2tf(float f) {
    uint32_t u;
    asm("cvt.rna.tf32.f32 %0, %1;" : "=r"(u) : "f"(f));
    return u;
}
__device__ __forceinline__ void mma_tf32(float* c, const uint32_t* a, const uint32_t* b) {
    asm volatile("mma.sync.aligned.m16n8k8.row.col.f32.tf32.tf32.f32 "
                 "{%0,%1,%2,%3}, {%4,%5,%6,%7}, {%8,%9}, {%0,%1,%2,%3};"
                 : "+f"(c[0]), "+f"(c[1]), "+f"(c[2]), "+f"(c[3])
                 : "r"(a[0]), "r"(a[1]), "r"(a[2]), "r"(a[3]), "r"(b[0]), "r"(b[1]));
}

// ---------------- counting sort of edges by dst ----------------
__global__ void hist_kernel(const int* __restrict__ ei) {
    int e = blockIdx.x * blockDim.x + threadIdx.x;
    if (e < E_EDGES) atomicAdd(&g_hist[ei[E_EDGES + e]], 1);
}

__global__ void prefix_kernel() {
    __shared__ int part[1024];
    int tid = threadIdx.x;
    int base = tid * 6;
    int loc[6];
    int s = 0;
#pragma unroll
    for (int i = 0; i < 6; i++) {
        int v = (base + i < N_NODES) ? g_hist[base + i] : 0;
        loc[i] = s; s += v;
    }
    part[tid] = s;
    __syncthreads();
    for (int d = 1; d < 1024; d <<= 1) {
        int v = 0;
        if (tid >= d) v = part[tid - d];
        __syncthreads();
        if (tid >= d) part[tid] += v;
        __syncthreads();
    }
    int excl = (tid == 0) ? 0 : part[tid - 1];
#pragma unroll
    for (int i = 0; i < 6; i++)
        if (base + i < N_NODES) g_off[base + i] = excl + loc[i];
    if (tid == 1023) g_off[N_NODES] = part[1023];
}

// sort + build contiguous edge-record stream {src, u0, u1, u2}
__global__ void sort_kernel(const int* __restrict__ ei, const float* __restrict__ ea) {
    int e = blockIdx.x * blockDim.x + threadIdx.x;
    if (e < E_EDGES) {
        int d = ei[E_EDGES + e];
        int src = ei[e];
        float u0 = ea[3 * e] * 4.f, u1 = ea[3 * e + 1] * 4.f, u2 = ea[3 * e + 2] * 4.f;
        int p = atomicAdd(&g_cur[d], 1);
        g_rec[g_off[d] + p] = make_float4(__int_as_float(src), u0, u1, u2);
    }
}

// ---------------- pack transposed weights: g_W*[n, k] = W[k, n] ----------------
__global__ void pack_kernel(const float* __restrict__ Wxr, const float* __restrict__ Wxz,
                            const float* __restrict__ Wxn, const float* __restrict__ Whr,
                            const float* __restrict__ Whz) {
    int stride = gridDim.x * blockDim.x;
    for (int i = blockIdx.x * blockDim.x + threadIdx.x; i < NX * KX; i += stride) {
        int n = i / KX, k = i % KX;
        int g = n >> 6, o = n & 63;
        const float* W = (g == 0) ? Wxr : ((g == 1) ? Wxz : Wxn);
        g_Wx[i] = W[k * 64 + o];
    }
    for (int i = blockIdx.x * blockDim.x + threadIdx.x; i < NH * KH; i += stride) {
        int n = i / KH, k = i % KH;
        int g = n >> 6, o = n & 63;
        g_Wh[i] = ((g == 0) ? Whr : Whz)[k * 64 + o];
    }
}

// ---------------- per-dst accumulation: no global atomics, 8-edge prefetch groups ----------------
// One block per dst. smem T row [125][96] (x ch 0..31, h ch 32..95), stride 97 (bank skew).
// Warp w owns channels [w*12, w*12+12): disjoint across warps -> no races.
// Within a warp: lane=(corner,cl); 8 corners of one edge hit 8 distinct kernel idx -> distinct rows.
#define UNR 8
__global__ void __launch_bounds__(256) accum_kernel(const float* __restrict__ x,
                                                    const float* __restrict__ h) {
    __shared__ float sT[125 * 97];    // 48500 B
    const int tid = threadIdx.x;
    const int dst = blockIdx.x;
    for (int i = tid; i < 125 * 97; i += 256) sT[i] = 0.f;
    __syncthreads();

    const int wid = tid >> 5, lane = tid & 31;
    const int corner = lane >> 2, cl = lane & 3;
    const int chb = wid * 12 + cl;
    const int b0 = corner & 1, b1 = (corner >> 1) & 1, b2 = (corner >> 2) & 1;
    // per-thread channel sources are fixed: precompute base pointers
    const float* srcp[3];
    int chOff[3];
#pragma unroll
    for (int c = 0; c < 3; c++) {
        int ch = chb + 4 * c;
        if (ch < 32) { srcp[c] = x; chOff[c] = ch;      }
        else         { srcp[c] = h; chOff[c] = ch - 32; }
    }
    const int rowlen0 = (chb < 32) ? CIN : CHID;   // unused placeholder avoidance
    (void)rowlen0;

    const int e0 = g_off[dst], e1 = g_off[dst + 1];
    for (int j = e0; j < e1; j += UNR) {
        float4 rec[UNR];
        float v[UNR][3];
#pragma unroll
        for (int t = 0; t < UNR; t++)
            rec[t] = (j + t < e1) ? g_rec[j + t] : make_float4(0.f, 0.f, 0.f, 0.f);
#pragma unroll
        for (int t = 0; t < UNR; t++) {
            int src = __float_as_int(rec[t].x);
#pragma unroll
            for (int c = 0; c < 3; c++) {
                int len = (chb + 4 * c < 32) ? CIN : CHID;
                v[t][c] = __ldg(srcp[c] + src * len + chOff[c]);
            }
        }
#pragma unroll
        for (int t = 0; t < UNR; t++) {
            if (j + t >= e1) break;
            float u0 = rec[t].y, u1 = rec[t].z, u2 = rec[t].w;
            int i0 = min(max((int)floorf(u0), 0), 3);
            int i1 = min(max((int)floorf(u1), 0), 3);
            int i2 = min(max((int)floorf(u2), 0), 3);
            float f0 = u0 - (float)i0, f1 = u1 - (float)i1, f2 = u2 - (float)i2;
            int idx = (i0 + b0) * 25 + (i1 + b1) * 5 + (i2 + b2);
            float basis = (b0 ? f0 : 1.f - f0) * (b1 ? f1 : 1.f - f1) * (b2 ? f2 : 1.f - f2);
            float* row = sT + idx * 97;
#pragma unroll
            for (int c = 0; c < 3; c++)
                row[chb + 4 * c] += basis * v[t][c];
        }
    }
    __syncthreads();

    // dense write-out (replaces memset + atomics)
    const long long o = (long long)dst;
    for (int i = tid; i < KX; i += 256)
        g_Tx[o * KX + i] = sT[(i >> 5) * 97 + (i & 31)];
    for (int i = tid; i < KH; i += 256)
        g_Th[o * KH + i] = sT[(i >> 6) * 97 + 32 + (i & 63)];
}

// ---------------- tensor-core GEMM via mma.sync tf32 ----------------
// WHICH=0: 47 CTAs, full N=192. WHICH=1: 94 CTAs, N-tile of 64. One wave total (141 CTAs).
template <int WHICH, int TILEN>
__device__ __forceinline__ void gemm_body(float* smf, int mtile, int n0) {
    constexpr int NB  = WHICH ? NH : NX;
    constexpr int KD  = WHICH ? KH : KX;
    constexpr int NIT = KD / BK;          // 250 / 125
    constexpr int WN  = TILEN / 2;        // 96 / 32
    constexpr int NT  = WN / 8;           // 12 / 4
    constexpr int A_FL = BM * ASTRIDE;    // 4608
    constexpr int B_FL = TILEN * ASTRIDE;

    const int tid = threadIdx.x;
    const int wid = tid >> 5, lane = tid & 31;
    const int wm = wid & 3, wn = wid >> 2;
    const int m0 = mtile * BM;
    const float* __restrict__ A  = WHICH ? g_Th : g_Tx;
    const float* __restrict__ Bw = WHICH ? g_Wh : g_Wx;
    float* __restrict__ C        = WHICH ? g_convh : g_convx;

    const uint32_t sbase = smem_u32(smf);
    const uint32_t aoff[2] = {0u, (uint32_t)A_FL * 4u};
    const uint32_t boff[2] = {(uint32_t)(2 * A_FL) * 4u, (uint32_t)(2 * A_FL + B_FL) * 4u};

    auto load_tiles = [&](int k0, int buf) {
#pragma unroll
        for (int it = 0; it < 4; it++) {                    // A: 1024 chunks
            int chunk = tid + it * 256;
            int row = chunk >> 3, c = chunk & 7;
            int gr = m0 + row;
            cp_async16(sbase + aoff[buf] + (uint32_t)(row * ASTRIDE * 4 + c * 16),
                       A + (long long)gr * KD + k0 + c * 4, (gr < N_NODES) ? 16 : 0);
        }
#pragma unroll
        for (int it = 0; it < TILEN * 8 / 256; it++) {      // B: TILEN*8 chunks
            int chunk = tid + it * 256;
            int row = chunk >> 3, c = chunk & 7;
            cp_async16(sbase + boff[buf] + (uint32_t)(row * ASTRIDE * 4 + c * 16),
                       Bw + (long long)(n0 + row) * KD + k0 + c * 4, 16);
        }
        cp_commit();
    };

    float acc[2][NT][4] = {};

    load_tiles(0, 0);
    cp_wait0();
    __syncthreads();

    int cur = 0;
    for (int kt = 0; kt < NIT; kt++) {
        if (kt + 1 < NIT) load_tiles((kt + 1) * BK, cur ^ 1);

        const float* As = smf + (aoff[cur] >> 2);
        const float* Bs = smf + (boff[cur] >> 2);
        const int r0  = wm * 32 + (lane >> 2);
        const int n0r = wn * WN + (lane >> 2);
        const int kc  = lane & 3;
#pragma unroll
        for (int ks = 0; ks < 4; ks++) {
            const int k8 = ks * 8;
            uint32_t a[2][4];
#pragma unroll
            for (int mt = 0; mt < 2; mt++) {
                int r = r0 + mt * 16;
                a[mt][0] = f2tf(As[r * ASTRIDE + k8 + kc]);
                a[mt][1] = f2tf(As[(r + 8) * ASTRIDE + k8 + kc]);
                a[mt][2] = f2tf(As[r * ASTRIDE + k8 + kc + 4]);
                a[mt][3] = f2tf(As[(r + 8) * ASTRIDE + k8 + kc + 4]);
            }
            uint32_t bf[NT][2];
#pragma unroll
            for (int nt = 0; nt < NT; nt++) {
                int nr = n0r + nt * 8;
                bf[nt][0] = f2tf(Bs[nr * ASTRIDE + k8 + kc]);
                bf[nt][1] = f2tf(Bs[nr * ASTRIDE + k8 + kc + 4]);
            }
#pragma unroll
            for (int mt = 0; mt < 2; mt++)
#pragma unroll
                for (int nt = 0; nt < NT; nt++)
                    mma_tf32(acc[mt][nt], a[mt], bf[nt]);
        }

        if (kt + 1 < NIT) cp_wait0();
        __syncthreads();
        cur ^= 1;
    }

#pragma unroll
    for (int mt = 0; mt < 2; mt++) {
        int r = m0 + wm * 32 + mt * 16 + (lane >> 2);
#pragma unroll
        for (int nt = 0; nt < NT; nt++) {
            int col = n0 + wn * WN + nt * 8 + (lane & 3) * 2;
            if (r < N_NODES)
                *reinterpret_cast<float2*>(&C[(long long)r * NB + col]) =
                    make_float2(acc[mt][nt][0], acc[mt][nt][1]);
            if (r + 8 < N_NODES)
                *reinterpret_cast<float2*>(&C[(long long)(r + 8) * NB + col]) =
                    make_float2(acc[mt][nt][2], acc[mt][nt][3]);
        }
    }
}

__global__ void __launch_bounds__(256, 1) gemm_mma() {
    extern __shared__ float smf[];
    if (blockIdx.x < MT) {
        gemm_body<0, NX>(smf, blockIdx.x, 0);
    } else {
        int b = blockIdx.x - MT;
        gemm_body<1, 64>(smf, b >> 1, (b & 1) * 64);
    }
}
#define GEMM_SMEM ((2 * BM * ASTRIDE + 2 * NX * ASTRIDE) * 4)   // 92160 B

// ---------------- fused epilogue: roots cached in smem, 16 nodes/block ----------------
#define FN_PER_BLK 16
#define FS_FLOATS (14336 + 5 * 64)
__global__ void __launch_bounds__(256) final_kernel(
        const float* __restrict__ x, const float* __restrict__ h,
        const float* __restrict__ root_xr, const float* __restrict__ b_xr,
        const float* __restrict__ root_hr, const float* __restrict__ b_hr,
        const float* __restrict__ root_xz, const float* __restrict__ b_xz,
        const float* __restrict__ root_hz, const float* __restrict__ b_hz,
        const float* __restrict__ root_xn, const float* __restrict__ b_xn,
        float* __restrict__ out) {
    extern __shared__ float fs[];
    const int tid = threadIdx.x;
    for (int i = tid; i < 2048; i += 256) {
        fs[i]        = root_xr[i];
        fs[2048 + i] = root_xz[i];
        fs[4096 + i] = root_xn[i];
    }
    for (int i = tid; i < 4096; i += 256) {
        fs[6144 + i]  = root_hr[i];
        fs[10240 + i] = root_hz[i];
    }
    if (tid < 64) {
        fs[14336 + tid] = b_xr[tid];
        fs[14400 + tid] = b_hr[tid];
        fs[14464 + tid] = b_xz[tid];
        fs[14528 + tid] = b_hz[tid];
        fs[14592 + tid] = b_xn[tid];
    }
    __syncthreads();

    const int o = tid & 63, q = tid >> 6;
    const int nb = blockIdx.x * FN_PER_BLK;
#pragma unroll
    for (int it = 0; it < FN_PER_BLK / 4; it++) {
        int n = nb + it * 4 + q;
        if (n >= N_NODES) continue;
        float inv = 1.f / fmaxf((float)g_hist[n], 1.f);
        float cxr  = g_convx[n * NX + o] * inv;
        float cxz  = g_convx[n * NX + 64 + o] * inv;
        float cxn  = g_convx[n * NX + 128 + o] * inv;
        float chr_ = g_convh[n * NH + o] * inv;
        float chz  = g_convh[n * NH + 64 + o] * inv;

        float rxr = 0.f, rxz = 0.f, rxn = 0.f;
#pragma unroll
        for (int i = 0; i < CIN; i++) {
            float xi = x[n * CIN + i];
            rxr += xi * fs[i * 64 + o];
            rxz += xi * fs[2048 + i * 64 + o];
            rxn += xi * fs[4096 + i * 64 + o];
        }
        float rhr = 0.f, rhz = 0.f;
#pragma unroll
        for (int i = 0; i < CHID; i++) {
            float hi = h[n * CHID + i];
            rhr += hi * fs[6144 + i * 64 + o];
            rhz += hi * fs[10240 + i * 64 + o];
        }

        float hr_out = chr_ + rhr + fs[14400 + o];
        float r = 1.f / (1.f + expf(-(cxr + rxr + fs[14336 + o] + hr_out)));
        float z = 1.f / (1.f + expf(-(cxz + rxz + fs[14464 + o] + chz + rhz + fs[14528 + o])));
        float ng = tanhf(cxn + rxn + fs[14592 + o] + r * hr_out);
        out[n * CHID + o] = (1.f - z) * ng + z * h[n * CHID + o];
    }
}

// ---------------- host launch ----------------
extern "C" void kernel_launch(void* const* d_in, const int* in_sizes, int n_in,
                              void* d_out, int out_size) {
    const float* x       = (const float*)d_in[0];
    const float* h       = (const float*)d_in[1];
    const int*   ei      = (const int*)  d_in[2];
    const float* ea      = (const float*)d_in[3];
    const float* W_xr    = (const float*)d_in[4];
    const float* root_xr = (const float*)d_in[5];
    const float* b_xr    = (const float*)d_in[6];
    const float* W_hr    = (const float*)d_in[7];
    const float* root_hr = (const float*)d_in[8];
    const float* b_hr    = (const float*)d_in[9];
    const float* W_xz    = (const float*)d_in[10];
    const float* root_xz = (const float*)d_in[11];
    const float* b_xz    = (const float*)d_in[12];
    const float* W_hz    = (const float*)d_in[13];
    const float* root_hz = (const float*)d_in[14];
    const float* b_hz    = (const float*)d_in[15];
    const float* W_xn    = (const float*)d_in[16];
    const float* root_xn = (const float*)d_in[17];
    const float* b_xn    = (const float*)d_in[18];
    float* out = (float*)d_out;

    void *pHist, *pCur;
    cudaGetSymbolAddress(&pHist, g_hist);
    cudaGetSymbolAddress(&pCur, g_cur);
    cudaMemsetAsync(pHist, 0, N_NODES * 4);
    cudaMemsetAsync(pCur, 0, N_NODES * 4);

    hist_kernel<<<(E_EDGES + 255) / 256, 256>>>(ei);
    prefix_kernel<<<1, 1024>>>();
    sort_kernel<<<(E_EDGES + 255) / 256, 256>>>(ei, ea);

    pack_kernel<<<2048, 256>>>(W_xr, W_xz, W_xn, W_hr, W_hz);

    accum_kernel<<<N_NODES, 256>>>(x, h);

    cudaFuncSetAttribute(gemm_mma, cudaFuncAttributeMaxDynamicSharedMemorySize, GEMM_SMEM);
    gemm_mma<<<MT + 2 * MT, 256, GEMM_SMEM>>>();

    cudaFuncSetAttribute(final_kernel, cudaFuncAttributeMaxDynamicSharedMemorySize,
                         FS_FLOATS * 4);
    final_kernel<<<(N_NODES + FN_PER_BLK - 1) / FN_PER_BLK, 256, FS_FLOATS * 4>>>(
        x, h, root_xr, b_xr, root_hr, b_hr, root_xz, b_xz, root_hz, b_hz,
        root_xn, b_xn, out);
}

// round 15
// speedup vs baseline: 9.3360x; 1.1185x over previous
#include <cuda_runtime.h>
#include <cuda_fp16.h>
#include <math.h>
#include <stdint.h>

// ---------------- problem constants ----------------
#define N_NODES 6000
#define E_EDGES 192000
#define CIN     32
#define CHID    64
#define KK      125
#define NX      192          // 3 gates * 64 (xr | xz | xn)
#define NH      128          // 2 gates * 64 (hr | hz)
#define KX      (KK * CIN)   // 4000
#define KH      (KK * CHID)  // 8000
#define MT      47           // ceil(6000/128) M tiles

// GEMM tiling (fp16)
#define BM 128
#define BK 32
#define STH 40               // padded halves per smem row (80 B, conflict-free)

// ---------------- static device scratch ----------------
__device__ __align__(1024) __half g_Tx[(size_t)N_NODES * KX];   // 48 MB
__device__ __align__(1024) __half g_Th[(size_t)N_NODES * KH];   // 96 MB
__device__ float g_convx[N_NODES * NX];
__device__ float g_convh[N_NODES * NH];
__device__ __align__(1024) __half g_Wx[NX * KX];                // transposed [N,K]
__device__ __align__(1024) __half g_Wh[NH * KH];                // transposed [N,K]
__device__ int g_hist[N_NODES];       // edges per dst (= degree)
__device__ int g_cur[N_NODES];
__device__ int g_off[N_NODES + 1];
__device__ __align__(16) float4 g_rec[E_EDGES];   // sorted {src, u0, u1, u2}

// ---------------- PTX helpers (plain sm_80/90 — nothing 'a'-gated) ----------------
__device__ __forceinline__ uint32_t smem_u32(const void* p) {
    uint32_t a;
    asm("{ .reg .u64 t; cvta.to.shared.u64 t, %1; cvt.u32.u64 %0, t; }" : "=r"(a) : "l"(p));
    return a;
}
__device__ __forceinline__ void cp_async16(uint32_t dst, const void* src, int sz) {
    asm volatile("cp.async.cg.shared.global [%0], [%1], 16, %2;"
                 :: "r"(dst), "l"(src), "r"(sz) : "memory");
}
__device__ __forceinline__ void cp_commit() { asm volatile("cp.async.commit_group;" ::: "memory"); }
__device__ __forceinline__ void cp_wait0()  { asm volatile("cp.async.wait_group 0;" ::: "memory"); }

__device__ __forceinline__ void mma_f16(float* c, const uint32_t* a, const uint32_t* b) {
    asm volatile("mma.sync.aligned.m16n8k16.row.col.f32.f16.f16.f32 "
                 "{%0,%1,%2,%3}, {%4,%5,%6,%7}, {%8,%9}, {%0,%1,%2,%3};"
                 : "+f"(c[0]), "+f"(c[1]), "+f"(c[2]), "+f"(c[3])
                 : "r"(a[0]), "r"(a[1]), "r"(a[2]), "r"(a[3]), "r"(b[0]), "r"(b[1]));
}

// ---------------- counting sort of edges by dst ----------------
__global__ void hist_kernel(const int* __restrict__ ei) {
    int e = blockIdx.x * blockDim.x + threadIdx.x;
    if (e < E_EDGES) atomicAdd(&g_hist[ei[E_EDGES + e]], 1);
}

__global__ void prefix_kernel() {
    __shared__ int part[1024];
    int tid = threadIdx.x;
    int base = tid * 6;
    int loc[6];
    int s = 0;
#pragma unroll
    for (int i = 0; i < 6; i++) {
        int v = (base + i < N_NODES) ? g_hist[base + i] : 0;
        loc[i] = s; s += v;
    }
    part[tid] = s;
    __syncthreads();
    for (int d = 1; d < 1024; d <<= 1) {
        int v = 0;
        if (tid >= d) v = part[tid - d];
        __syncthreads();
        if (tid >= d) part[tid] += v;
        __syncthreads();
    }
    int excl = (tid == 0) ? 0 : part[tid - 1];
#pragma unroll
    for (int i = 0; i < 6; i++)
        if (base + i < N_NODES) g_off[base + i] = excl + loc[i];
    if (tid == 1023) g_off[N_NODES] = part[1023];
}

// sort + build contiguous edge-record stream {src, u0, u1, u2}
__global__ void sort_kernel(const int* __restrict__ ei, const float* __restrict__ ea) {
    int e = blockIdx.x * blockDim.x + threadIdx.x;
    if (e < E_EDGES) {
        int d = ei[E_EDGES + e];
        int src = ei[e];
        float u0 = ea[3 * e] * 4.f, u1 = ea[3 * e + 1] * 4.f, u2 = ea[3 * e + 2] * 4.f;
        int p = atomicAdd(&g_cur[d], 1);
        g_rec[g_off[d] + p] = make_float4(__int_as_float(src), u0, u1, u2);
    }
}

// ---------------- pack transposed fp16 weights: g_W*[n, k] = half(W[k, n]) ----------------
__global__ void pack_kernel(const float* __restrict__ Wxr, const float* __restrict__ Wxz,
                            const float* __restrict__ Wxn, const float* __restrict__ Whr,
                            const float* __restrict__ Whz) {
    int stride = gridDim.x * blockDim.x;
    for (int i = blockIdx.x * blockDim.x + threadIdx.x; i < NX * KX; i += stride) {
        int n = i / KX, k = i % KX;
        int g = n >> 6, o = n & 63;
        const float* W = (g == 0) ? Wxr : ((g == 1) ? Wxz : Wxn);
        g_Wx[i] = __float2half_rn(W[k * 64 + o]);
    }
    for (int i = blockIdx.x * blockDim.x + threadIdx.x; i < NH * KH; i += stride) {
        int n = i / KH, k = i % KH;
        int g = n >> 6, o = n & 63;
        g_Wh[i] = __float2half_rn(((g == 0) ? Whr : Whz)[k * 64 + o]);
    }
}

// ---------------- per-dst accumulation: no global atomics, 8-edge prefetch groups ----------------
#define UNR 8
__global__ void __launch_bounds__(256) accum_kernel(const float* __restrict__ x,
                                                    const float* __restrict__ h) {
    __shared__ float sT[125 * 97];    // 48500 B
    const int tid = threadIdx.x;
    const int dst = blockIdx.x;
    for (int i = tid; i < 125 * 97; i += 256) sT[i] = 0.f;
    __syncthreads();

    const int wid = tid >> 5, lane = tid & 31;
    const int corner = lane >> 2, cl = lane & 3;
    const int chb = wid * 12 + cl;
    const int b0 = corner & 1, b1 = (corner >> 1) & 1, b2 = (corner >> 2) & 1;
    const float* srcp[3];
    int chOff[3];
#pragma unroll
    for (int c = 0; c < 3; c++) {
        int ch = chb + 4 * c;
        if (ch < 32) { srcp[c] = x; chOff[c] = ch;      }
        else         { srcp[c] = h; chOff[c] = ch - 32; }
    }

    const int e0 = g_off[dst], e1 = g_off[dst + 1];
    for (int j = e0; j < e1; j += UNR) {
        float4 rec[UNR];
        float v[UNR][3];
#pragma unroll
        for (int t = 0; t < UNR; t++)
            rec[t] = (j + t < e1) ? g_rec[j + t] : make_float4(0.f, 0.f, 0.f, 0.f);
#pragma unroll
        for (int t = 0; t < UNR; t++) {
            int src = __float_as_int(rec[t].x);
#pragma unroll
            for (int c = 0; c < 3; c++) {
                int len = (chb + 4 * c < 32) ? CIN : CHID;
                v[t][c] = __ldg(srcp[c] + src * len + chOff[c]);
            }
        }
#pragma unroll
        for (int t = 0; t < UNR; t++) {
            if (j + t >= e1) break;
            float u0 = rec[t].y, u1 = rec[t].z, u2 = rec[t].w;
            int i0 = min(max((int)floorf(u0), 0), 3);
            int i1 = min(max((int)floorf(u1), 0), 3);
            int i2 = min(max((int)floorf(u2), 0), 3);
            float f0 = u0 - (float)i0, f1 = u1 - (float)i1, f2 = u2 - (float)i2;
            int idx = (i0 + b0) * 25 + (i1 + b1) * 5 + (i2 + b2);
            float basis = (b0 ? f0 : 1.f - f0) * (b1 ? f1 : 1.f - f1) * (b2 ? f2 : 1.f - f2);
            float* row = sT + idx * 97;
#pragma unroll
            for (int c = 0; c < 3; c++)
                row[chb + 4 * c] += basis * v[t][c];
        }
    }
    __syncthreads();

    // dense fp16 write-out
    __half2* txo = reinterpret_cast<__half2*>(g_Tx) + (size_t)dst * (KX / 2);
    for (int i = tid; i < KX / 2; i += 256) {
        int k = i >> 4, c = i & 15;
        txo[i] = __floats2half2_rn(sT[k * 97 + 2 * c], sT[k * 97 + 2 * c + 1]);
    }
    __half2* tho = reinterpret_cast<__half2*>(g_Th) + (size_t)dst * (KH / 2);
    for (int i = tid; i < KH / 2; i += 256) {
        int k = i >> 5, c = i & 31;
        tho[i] = __floats2half2_rn(sT[k * 97 + 32 + 2 * c], sT[k * 97 + 32 + 2 * c + 1]);
    }
}

// ---------------- tensor-core GEMM via mma.sync fp16 (m16n8k16) ----------------
// WHICH=0: 47 CTAs, full N=192. WHICH=1: 94 CTAs, N-tile of 64. One wave (141 CTAs).
template <int WHICH, int TILEN>
__device__ __forceinline__ void gemm_body(char* smc, int mtile, int n0) {
    constexpr int NB  = WHICH ? NH : NX;
    constexpr int KD  = WHICH ? KH : KX;
    constexpr int NIT = KD / BK;          // 250 / 125
    constexpr int WN  = TILEN / 2;        // 96 / 32
    constexpr int NT  = WN / 8;           // 12 / 4
    constexpr int A_BY = BM * STH * 2;    // 10240
    constexpr int B_BY = TILEN * STH * 2;

    const int tid = threadIdx.x;
    const int wid = tid >> 5, lane = tid & 31;
    const int wm = wid & 3, wn = wid >> 2;
    const int gid = lane >> 2, tc = lane & 3;
    const int m0 = mtile * BM;
    const __half* __restrict__ A  = WHICH ? g_Th : g_Tx;
    const __half* __restrict__ Bw = WHICH ? g_Wh : g_Wx;
    float* __restrict__ C         = WHICH ? g_convh : g_convx;

    const uint32_t sbase = smem_u32(smc);
    const uint32_t aoff[2] = {0u, (uint32_t)A_BY};
    const uint32_t boff[2] = {(uint32_t)(2 * A_BY), (uint32_t)(2 * A_BY + B_BY)};

    auto load_tiles = [&](int k0, int buf) {
#pragma unroll
        for (int it = 0; it < 2; it++) {                    // A: 512 chunks of 16B
            int chunk = tid + it * 256;
            int row = chunk >> 2, c = chunk & 3;
            int gr = m0 + row;
            cp_async16(sbase + aoff[buf] + (uint32_t)(row * STH * 2 + c * 16),
                       A + (size_t)gr * KD + k0 + c * 8, (gr < N_NODES) ? 16 : 0);
        }
#pragma unroll
        for (int it = 0; it < TILEN * 4 / 256; it++) {      // B: TILEN*4 chunks
            int chunk = tid + it * 256;
            int row = chunk >> 2, c = chunk & 3;
            cp_async16(sbase + boff[buf] + (uint32_t)(row * STH * 2 + c * 16),
                       Bw + (size_t)(n0 + row) * KD + k0 + c * 8, 16);
        }
        cp_commit();
    };

    float acc[2][NT][4] = {};

    load_tiles(0, 0);
    cp_wait0();
    __syncthreads();

    int cur = 0;
    for (int kt = 0; kt < NIT; kt++) {
        if (kt + 1 < NIT) load_tiles((kt + 1) * BK, cur ^ 1);

        const __half* As = reinterpret_cast<const __half*>(smc + aoff[cur]);
        const __half* Bs = reinterpret_cast<const __half*>(smc + boff[cur]);
        const int r0  = wm * 32 + gid;
        const int n0r = wn * WN + gid;
#pragma unroll
        for (int ks = 0; ks < 2; ks++) {
            const int k16 = ks * 16;
            uint32_t a[2][4];
#pragma unroll
            for (int mt = 0; mt < 2; mt++) {
                int r = r0 + mt * 16;
                a[mt][0] = *reinterpret_cast<const uint32_t*>(&As[r * STH + k16 + 2 * tc]);
                a[mt][1] = *reinterpret_cast<const uint32_t*>(&As[(r + 8) * STH + k16 + 2 * tc]);
                a[mt][2] = *reinterpret_cast<const uint32_t*>(&As[r * STH + k16 + 8 + 2 * tc]);
                a[mt][3] = *reinterpret_cast<const uint32_t*>(&As[(r + 8) * STH + k16 + 8 + 2 * tc]);
            }
            uint32_t bf[NT][2];
#pragma unroll
            for (int nt = 0; nt < NT; nt++) {
                int nr = n0r + nt * 8;
                bf[nt][0] = *reinterpret_cast<const uint32_t*>(&Bs[nr * STH + k16 + 2 * tc]);
                bf[nt][1] = *reinterpret_cast<const uint32_t*>(&Bs[nr * STH + k16 + 8 + 2 * tc]);
            }
#pragma unroll
            for (int mt = 0; mt < 2; mt++)
#pragma unroll
                for (int nt = 0; nt < NT; nt++)
                    mma_f16(acc[mt][nt], a[mt], bf[nt]);
        }

        if (kt + 1 < NIT) cp_wait0();
        __syncthreads();
        cur ^= 1;
    }

#pragma unroll
    for (int mt = 0; mt < 2; mt++) {
        int r = m0 + wm * 32 + mt * 16 + gid;
#pragma unroll
        for (int nt = 0; nt < NT; nt++) {
            int col = n0 + wn * WN + nt * 8 + tc * 2;
            if (r < N_NODES)
                *reinterpret_cast<float2*>(&C[(size_t)r * NB + col]) =
                    make_float2(acc[mt][nt][0], acc[mt][nt][1]);
            if (r + 8 < N_NODES)
                *reinterpret_cast<float2*>(&C[(size_t)(r + 8) * NB + col]) =
                    make_float2(acc[mt][nt][2], acc[mt][nt][3]);
        }
    }
}

__global__ void __launch_bounds__(256, 1) gemm_mma() {
    extern __shared__ char smc[];
    if (blockIdx.x < MT) {
        gemm_body<0, NX>(smc, blockIdx.x, 0);
    } else {
        int b = blockIdx.x - MT;
        gemm_body<1, 64>(smc, b >> 1, (b & 1) * 64);
    }
}
#define GEMM_SMEM (2 * BM * STH * 2 + 2 * NX * STH * 2)   // 51200 B

// ---------------- fused epilogue: roots cached in smem, 16 nodes/block ----------------
#define FN_PER_BLK 16
#define FS_FLOATS (14336 + 5 * 64)
__global__ void __launch_bounds__(256) final_kernel(
        const float* __restrict__ x, const float* __restrict__ h,
        const float* __restrict__ root_xr, const float* __restrict__ b_xr,
        const float* __restrict__ root_hr, const float* __restrict__ b_hr,
        const float* __restrict__ root_xz, const float* __restrict__ b_xz,
        const float* __restrict__ root_hz, const float* __restrict__ b_hz,
        const float* __restrict__ root_xn, const float* __restrict__ b_xn,
        float* __restrict__ out) {
    extern __shared__ float fs[];
    const int tid = threadIdx.x;
    for (int i = tid; i < 2048; i += 256) {
        fs[i]        = root_xr[i];
        fs[2048 + i] = root_xz[i];
        fs[4096 + i] = root_xn[i];
    }
    for (int i = tid; i < 4096; i += 256) {
        fs[6144 + i]  = root_hr[i];
        fs[10240 + i] = root_hz[i];
    }
    if (tid < 64) {
        fs[14336 + tid] = b_xr[tid];
        fs[14400 + tid] = b_hr[tid];
        fs[14464 + tid] = b_xz[tid];
        fs[14528 + tid] = b_hz[tid];
        fs[14592 + tid] = b_xn[tid];
    }
    __syncthreads();

    const int o = tid & 63, q = tid >> 6;
    const int nb = blockIdx.x * FN_PER_BLK;
#pragma unroll
    for (int it = 0; it < FN_PER_BLK / 4; it++) {
        int n = nb + it * 4 + q;
        if (n >= N_NODES) continue;
        float inv = 1.f / fmaxf((float)g_hist[n], 1.f);
        float cxr  = g_convx[n * NX + o] * inv;
        float cxz  = g_convx[n * NX + 64 + o] * inv;
        float cxn  = g_convx[n * NX + 128 + o] * inv;
        float chr_ = g_convh[n * NH + o] * inv;
        float chz  = g_convh[n * NH + 64 + o] * inv;

        float rxr = 0.f, rxz = 0.f, rxn = 0.f;
#pragma unroll
        for (int i = 0; i < CIN; i++) {
            float xi = x[n * CIN + i];
            rxr += xi * fs[i * 64 + o];
            rxz += xi * fs[2048 + i * 64 + o];
            rxn += xi * fs[4096 + i * 64 + o];
        }
        float rhr = 0.f, rhz = 0.f;
#pragma unroll
        for (int i = 0; i < CHID; i++) {
            float hi = h[n * CHID + i];
            rhr += hi * fs[6144 + i * 64 + o];
            rhz += hi * fs[10240 + i * 64 + o];
        }

        float hr_out = chr_ + rhr + fs[14400 + o];
        float r = 1.f / (1.f + expf(-(cxr + rxr + fs[14336 + o] + hr_out)));
        float z = 1.f / (1.f + expf(-(cxz + rxz + fs[14464 + o] + chz + rhz + fs[14528 + o])));
        float ng = tanhf(cxn + rxn + fs[14592 + o] + r * hr_out);
        out[n * CHID + o] = (1.f - z) * ng + z * h[n * CHID + o];
    }
}

// ---------------- host launch ----------------
extern "C" void kernel_launch(void* const* d_in, const int* in_sizes, int n_in,
                              void* d_out, int out_size) {
    const float* x       = (const float*)d_in[0];
    const float* h       = (const float*)d_in[1];
    const int*   ei      = (const int*)  d_in[2];
    const float* ea      = (const float*)d_in[3];
    const float* W_xr    = (const float*)d_in[4];
    const float* root_xr = (const float*)d_in[5];
    const float* b_xr    = (const float*)d_in[6];
    const float* W_hr    = (const float*)d_in[7];
    const float* root_hr = (const float*)d_in[8];
    const float* b_hr    = (const float*)d_in[9];
    const float* W_xz    = (const float*)d_in[10];
    const float* root_xz = (const float*)d_in[11];
    const float* b_xz    = (const float*)d_in[12];
    const float* W_hz    = (const float*)d_in[13];
    const float* root_hz = (const float*)d_in[14];
    const float* b_hz    = (const float*)d_in[15];
    const float* W_xn    = (const float*)d_in[16];
    const float* root_xn = (const float*)d_in[17];
    const float* b_xn    = (const float*)d_in[18];
    float* out = (float*)d_out;

    void *pHist, *pCur;
    cudaGetSymbolAddress(&pHist, g_hist);
    cudaGetSymbolAddress(&pCur, g_cur);
    cudaMemsetAsync(pHist, 0, N_NODES * 4);
    cudaMemsetAsync(pCur, 0, N_NODES * 4);

    hist_kernel<<<(E_EDGES + 255) / 256, 256>>>(ei);
    prefix_kernel<<<1, 1024>>>();
    sort_kernel<<<(E_EDGES + 255) / 256, 256>>>(ei, ea);

    pack_kernel<<<2048, 256>>>(W_xr, W_xz, W_xn, W_hr, W_hz);

    accum_kernel<<<N_NODES, 256>>>(x, h);

    cudaFuncSetAttribute(gemm_mma, cudaFuncAttributeMaxDynamicSharedMemorySize, GEMM_SMEM);
    gemm_mma<<<MT + 2 * MT, 256, GEMM_SMEM>>>();

    cudaFuncSetAttribute(final_kernel, cudaFuncAttributeMaxDynamicSharedMemorySize,
                         FS_FLOATS * 4);
    final_kernel<<<(N_NODES + FN_PER_BLK - 1) / FN_PER_BLK, 256, FS_FLOATS * 4>>>(
        x, h, root_xr, b_xr, root_hr, b_hr, root_xz, b_xz, root_hz, b_hz,
        root_xn, b_xn, out);
}